// round 4
// baseline (speedup 1.0000x reference)
#include <cuda_runtime.h>
#include <cstdint>

// VIN fused kernel, f32x2-packed (Blackwell FFMA2).
//   phi   = obs @ W_phi.T + b_phi        [B,48]
//   V     = 20-step value iteration on 4x4 grid (rin=phi[0:16], rout=phi[16:32], p=phi[32:48])
//   logit = obs @ W_logit.T + b_logit    [B,5]
//   V_    = V[first nonzero of obs channel-1, else cell 5]
// Output: out[0:5B] = logit row-major, out[5B:6B] = V_.

#define KITERS 20

typedef unsigned long long u64;

// ---------- f32x2 helpers (packed pair carried as b64) ----------
__device__ __forceinline__ u64 f2fma(u64 a, u64 b, u64 c) {
    u64 d;
    asm("fma.rn.f32x2 %0, %1, %2, %3;" : "=l"(d) : "l"(a), "l"(b), "l"(c));
    return d;
}
__device__ __forceinline__ u64 pk(float lo, float hi) {
    u64 d;
    asm("mov.b64 %0, {%1, %2};" : "=l"(d) : "f"(lo), "f"(hi));
    return d;
}
__device__ __forceinline__ float lof(u64 x) {
    float lo, hi;
    asm("mov.b64 {%0, %1}, %2;" : "=f"(lo), "=f"(hi) : "l"(x));
    return lo;
}
__device__ __forceinline__ float hif(u64 x) {
    float lo, hi;
    asm("mov.b64 {%0, %1}, %2;" : "=f"(lo), "=f"(hi) : "l"(x));
    return hi;
}

// ---------- packed-weight scratch (built once per launch by prep kernel) ----------
__device__ u64 gW2[48 * 24];   // [k][jp] = {Wphi[2jp][k], Wphi[2jp+1][k]}
__device__ u64 gWl2[48 * 2];   // [k][p]  = {Wlog[2p][k],  Wlog[2p+1][k]}
__device__ float gWlS[48];     //          Wlog[4][k]
__device__ u64 gB2[24];        // {bphi[2j], bphi[2j+1]}
__device__ u64 gBl2[2];        // {blog[0],blog[1]}, {blog[2],blog[3]}
__device__ float gBl4;         // blog[4]

__global__ void prep_kernel(const float* __restrict__ Wphi,
                            const float* __restrict__ bphi,
                            const float* __restrict__ Wlog,
                            const float* __restrict__ blog)
{
    int t = blockIdx.x * blockDim.x + threadIdx.x;
    if (t < 1152) {                 // gW2
        int k = t / 24, jp = t % 24;
        gW2[t] = pk(Wphi[(2 * jp) * 48 + k], Wphi[(2 * jp + 1) * 48 + k]);
    }
    if (t < 96) {                   // gWl2
        int k = t / 2, p = t % 2;
        gWl2[t] = pk(Wlog[(2 * p) * 48 + k], Wlog[(2 * p + 1) * 48 + k]);
    }
    if (t < 48) gWlS[t] = Wlog[4 * 48 + t];
    if (t < 24) gB2[t] = pk(bphi[2 * t], bphi[2 * t + 1]);
    if (t < 2)  gBl2[t] = pk(blog[2 * t], blog[2 * t + 1]);
    if (t == 0) gBl4 = blog[4];
}

// ---------- main kernel ----------
__global__ __launch_bounds__(128)
void vin_kernel(const float* __restrict__ obs,
                float* __restrict__ out, int B)
{
    __shared__ __align__(16) u64 sW2[48 * 24];
    __shared__ __align__(16) u64 sWl2[48 * 2];
    __shared__ float sWlS[48];
    __shared__ u64 sB2[24];
    __shared__ u64 sBl2[2];
    __shared__ float sBl4;

    const int tid = threadIdx.x;
    for (int i = tid; i < 48 * 24; i += 128) sW2[i] = gW2[i];
    for (int i = tid; i < 96; i += 128) sWl2[i] = gWl2[i];
    if (tid < 48) sWlS[tid] = gWlS[tid];
    if (tid < 24) sB2[tid] = gB2[tid];
    if (tid < 2)  sBl2[tid] = gBl2[tid];
    if (tid == 0) sBl4 = gBl4;
    __syncthreads();

    const int r = blockIdx.x * 128 + tid;
    if (r >= B) return;

    // ---- load obs row ----
    float o[48];
    const float4* op = reinterpret_cast<const float4*>(obs + (size_t)r * 48);
#pragma unroll
    for (int i = 0; i < 12; i++) {
        float4 t = op[i];
        o[4 * i + 0] = t.x; o[4 * i + 1] = t.y;
        o[4 * i + 2] = t.z; o[4 * i + 3] = t.w;
    }

    // ---- agent-position mask (channel 1 = obs[3c+1]) ----
    unsigned mask = 0u;
#pragma unroll
    for (int c = 0; c < 16; c++)
        if (o[3 * c + 1] != 0.0f) mask |= (1u << c);

    // ---- packed GEMM: phi pairs + logits ----
    u64 phi2[24];
#pragma unroll
    for (int jp = 0; jp < 24; jp++) phi2[jp] = sB2[jp];
    u64 l01 = sBl2[0], l23 = sBl2[1];
    float l4 = sBl4;

#pragma unroll 8
    for (int k = 0; k < 48; k++) {
        const u64 ok2 = pk(o[k], o[k]);
        const ulonglong2* pw = reinterpret_cast<const ulonglong2*>(sW2 + k * 24);
#pragma unroll
        for (int q = 0; q < 12; q++) {
            ulonglong2 w = pw[q];
            phi2[2 * q + 0] = f2fma(ok2, w.x, phi2[2 * q + 0]);
            phi2[2 * q + 1] = f2fma(ok2, w.y, phi2[2 * q + 1]);
        }
        ulonglong2 wl = reinterpret_cast<const ulonglong2*>(sWl2)[k];
        l01 = f2fma(ok2, wl.x, l01);
        l23 = f2fma(ok2, wl.y, l23);
        l4  = fmaf(o[k], sWlS[k], l4);
    }

    // logits out
    {
        float* lo = out + (size_t)r * 5;
        lo[0] = lof(l01); lo[1] = hif(l01);
        lo[2] = lof(l23); lo[3] = hif(l23);
        lo[4] = l4;
    }

    // ---- value iteration ----
    // rin pairs = phi2[0..7], rout pairs = phi2[8..15], p pairs = phi2[16..23]
    // pair cp covers cells (2cp, 2cp+1); row rr owns pairs 2rr, 2rr+1.
    float ro[16];
#pragma unroll
    for (int cp = 0; cp < 8; cp++) { ro[2 * cp] = lof(phi2[8 + cp]); ro[2 * cp + 1] = hif(phi2[8 + cp]); }
    u64 rins[4];   // (rin[4r+1], rin[4r+2])
    float ps1[4], ps2[4], ri0[4], ri3[4];
#pragma unroll
    for (int rr = 0; rr < 4; rr++) {
        const int q0 = 2 * rr, q1 = q0 + 1;
        rins[rr] = pk(hif(phi2[q0]), lof(phi2[q1]));
        ps1[rr] = hif(phi2[16 + q0]);   // p[4r+1]
        ps2[rr] = lof(phi2[16 + q1]);   // p[4r+2]
        ri0[rr] = lof(phi2[q0]);        // rin[4r]
        ri3[rr] = hif(phi2[q1]);        // rin[4r+3]
    }

    u64 v2[8];
#pragma unroll
    for (int cp = 0; cp < 8; cp++) v2[cp] = 0ull;   // (0.0f, 0.0f)

#pragma unroll 4
    for (int it = 0; it < KITERS; it++) {
        // vertical candidates, fully packed
        u64 up2[8], dn2[8];
#pragma unroll
        for (int cp = 2; cp < 8; cp++) up2[cp] = f2fma(phi2[16 + cp], v2[cp - 2], phi2[cp - 2]);
#pragma unroll
        for (int cp = 0; cp < 6; cp++) dn2[cp] = f2fma(phi2[16 + cp], v2[cp + 2], phi2[cp + 2]);

        float nv[16];
#pragma unroll
        for (int rr = 0; rr < 4; rr++) {
            const int q0 = 2 * rr, q1 = q0 + 1;
            const float va0 = lof(v2[q0]), va1 = hif(v2[q0]);
            const float va2 = lof(v2[q1]), va3 = hif(v2[q1]);
            const u64 s = pk(va1, va2);                        // (v[4r+1], v[4r+2])
            const u64 R01 = f2fma(phi2[16 + q0], s, rins[rr]); // right cands of cells 4r,4r+1
            const u64 L23 = f2fma(phi2[16 + q1], s, rins[rr]); // left  cands of cells 4r+2,4r+3
            const float lf1 = fmaf(ps1[rr], va0, ri0[rr]);     // left  cand of cell 4r+1
            const float rt2 = fmaf(ps2[rr], va3, ri3[rr]);     // right cand of cell 4r+2

            // col 0 (left oob)
            float m0 = lof(R01);
            if (rr > 0) m0 = fmaxf(m0, lof(up2[q0]));
            if (rr < 3) m0 = fmaxf(m0, lof(dn2[q0]));
            m0 = fmaxf(m0, 0.0f);
            // col 1
            float m1 = fmaxf(lf1, hif(R01));
            if (rr > 0) m1 = fmaxf(m1, hif(up2[q0]));
            if (rr < 3) m1 = fmaxf(m1, hif(dn2[q0]));
            if (rr == 0 || rr == 3) m1 = fmaxf(m1, 0.0f);
            // col 2
            float m2 = fmaxf(lof(L23), rt2);
            if (rr > 0) m2 = fmaxf(m2, lof(up2[q1]));
            if (rr < 3) m2 = fmaxf(m2, lof(dn2[q1]));
            if (rr == 0 || rr == 3) m2 = fmaxf(m2, 0.0f);
            // col 3 (right oob)
            float m3 = hif(L23);
            if (rr > 0) m3 = fmaxf(m3, hif(up2[q1]));
            if (rr < 3) m3 = fmaxf(m3, hif(dn2[q1]));
            m3 = fmaxf(m3, 0.0f);

            nv[4 * rr + 0] = fmaxf(va0, m0 - ro[4 * rr + 0]);
            nv[4 * rr + 1] = fmaxf(va1, m1 - ro[4 * rr + 1]);
            nv[4 * rr + 2] = fmaxf(va2, m2 - ro[4 * rr + 2]);
            nv[4 * rr + 3] = fmaxf(va3, m3 - ro[4 * rr + 3]);
        }
#pragma unroll
        for (int cp = 0; cp < 8; cp++) v2[cp] = pk(nv[2 * cp], nv[2 * cp + 1]);
    }

    // ---- select V at first nonzero channel-1 cell (default cell 5) ----
    float vf[16];
#pragma unroll
    for (int cp = 0; cp < 8; cp++) { vf[2 * cp] = lof(v2[cp]); vf[2 * cp + 1] = hif(v2[cp]); }
    float Vsel = vf[5];
#pragma unroll
    for (int c = 15; c >= 0; c--)
        if (mask & (1u << c)) Vsel = vf[c];

    out[(size_t)5 * B + r] = Vsel;
}

extern "C" void kernel_launch(void* const* d_in, const int* in_sizes, int n_in,
                              void* d_out, int out_size)
{
    const float* obs  = (const float*)d_in[0];
    const float* Wphi = (const float*)d_in[1];
    const float* bphi = (const float*)d_in[2];
    const float* Wlog = (const float*)d_in[3];
    const float* blog = (const float*)d_in[4];
    float* out = (float*)d_out;
    const int B = in_sizes[0] / 48;

    prep_kernel<<<9, 128>>>(Wphi, bphi, Wlog, blog);
    vin_kernel<<<(B + 127) / 128, 128>>>(obs, out, B);
}